// round 8
// baseline (speedup 1.0000x reference)
#include <cuda_runtime.h>
#include <cuda_fp16.h>
#include <cuda_bf16.h>

#define N_NODES 100000
#define N_EDGES 1600000
#define IN_F 128
#define OUT_F 48
#define NBLK_SCAN ((N_NODES + 1023) / 1024)   // 98

// Scratch (__device__ globals; zero-initialized at load; no allocations allowed)
__device__ float  g_ssrc[N_NODES];                    // h . w_src
__device__ float  g_sdst[N_NODES];                    // h . w_dst
__device__ __half g_hh[(size_t)N_NODES * OUT_F];      // projected features (fp16, 96B rows)
__device__ int    g_cnt[N_NODES];                     // degree by dst (zero at entry!)
__device__ int    g_off[N_NODES];                     // CSR offsets
__device__ int    g_rank[N_EDGES];                    // edge rank within its dst segment
__device__ unsigned long long g_state[NBLK_SCAN];     // lookback state (zero at entry!)
__device__ unsigned long long g_edge[N_EDGES];        // packed {src, ex}

// ---------------------------------------------------------------------------
// GEMM + dst histogram (histogram also records each edge's rank within its
// dst segment -- the atomic's return value -- so the scatter needs no atomic).
// ---------------------------------------------------------------------------
__global__ void __launch_bounds__(128) k_gemm(
    const float* __restrict__ feat, const float* __restrict__ Ww,
    const float* __restrict__ Wb, const float* __restrict__ attnw,
    const int* __restrict__ dst)
{
    // --- histogram of dst (grid-stride; latency hides under the FMA wall) ---
    {
        int gsz = gridDim.x * 128;
        for (int e = blockIdx.x * 128 + threadIdx.x; e < N_EDGES; e += gsz)
            g_rank[e] = atomicAdd(&g_cnt[dst[e]], 1);
    }

    __shared__ unsigned long long sWp[IN_F][OUT_F / 2];
    __shared__ float sb[OUT_F], sws[OUT_F], swd[OUT_F];

    int tid = threadIdx.x;
    for (int i = tid; i < IN_F * (OUT_F / 2); i += 128) {
        int k  = i / (OUT_F / 2);
        int jj = i % (OUT_F / 2);
        float lo = Ww[(2 * jj) * IN_F + k];
        float hi = Ww[(2 * jj + 1) * IN_F + k];
        unsigned long long p;
        asm("mov.b64 %0, {%1, %2};" : "=l"(p) : "f"(lo), "f"(hi));
        sWp[k][jj] = p;
    }
    if (tid < OUT_F) {
        sb[tid]  = Wb[tid];
        sws[tid] = attnw[tid];
        swd[tid] = attnw[OUT_F + tid];
    }
    __syncthreads();

    long n0 = (long)blockIdx.x * 256 + tid;
    long n1 = n0 + 128;
    bool v0 = n0 < N_NODES, v1 = n1 < N_NODES;
    const float4* r0 = (const float4*)(feat + (v0 ? n0 : 0) * IN_F);
    const float4* r1 = (const float4*)(feat + (v1 ? n1 : 0) * IN_F);

    unsigned long long a0[OUT_F / 2], a1[OUT_F / 2];
#pragma unroll
    for (int jj = 0; jj < OUT_F / 2; jj++) {
        unsigned long long p;
        asm("mov.b64 %0, {%1, %2};" : "=l"(p) : "f"(sb[2 * jj]), "f"(sb[2 * jj + 1]));
        a0[jj] = p;
        a1[jj] = p;
    }

#pragma unroll 2
    for (int k4 = 0; k4 < IN_F / 4; k4++) {
        float4 f0 = r0[k4];
        float4 f1 = r1[k4];
        float fs0[4] = {f0.x, f0.y, f0.z, f0.w};
        float fs1[4] = {f1.x, f1.y, f1.z, f1.w};
#pragma unroll
        for (int u = 0; u < 4; u++) {
            unsigned long long ff0, ff1;
            asm("mov.b64 %0, {%1, %1};" : "=l"(ff0) : "f"(fs0[u]));
            asm("mov.b64 %0, {%1, %1};" : "=l"(ff1) : "f"(fs1[u]));
            int k = 4 * k4 + u;
#pragma unroll
            for (int jj = 0; jj < OUT_F / 2; jj++) {
                unsigned long long w = sWp[k][jj];
                asm("fma.rn.f32x2 %0, %1, %2, %0;" : "+l"(a0[jj]) : "l"(ff0), "l"(w));
                asm("fma.rn.f32x2 %0, %1, %2, %0;" : "+l"(a1[jj]) : "l"(ff1), "l"(w));
            }
        }
    }

    if (v0) {
        float s1 = 0.0f, s2 = 0.0f;
        unsigned hh[OUT_F / 2];
#pragma unroll
        for (int jj = 0; jj < OUT_F / 2; jj++) {
            float lo, hi;
            asm("mov.b64 {%0, %1}, %2;" : "=f"(lo), "=f"(hi) : "l"(a0[jj]));
            s1 += lo * sws[2 * jj] + hi * sws[2 * jj + 1];
            s2 += lo * swd[2 * jj] + hi * swd[2 * jj + 1];
            __half2 h2 = __floats2half2_rn(lo, hi);
            hh[jj] = *(unsigned*)&h2;
        }
        uint4* hr = (uint4*)(g_hh + (size_t)n0 * OUT_F);
#pragma unroll
        for (int i = 0; i < 6; i++)
            hr[i] = make_uint4(hh[4 * i], hh[4 * i + 1], hh[4 * i + 2], hh[4 * i + 3]);
        g_ssrc[n0] = s1;
        g_sdst[n0] = s2;
    }
    if (v1) {
        float s1 = 0.0f, s2 = 0.0f;
        unsigned hh[OUT_F / 2];
#pragma unroll
        for (int jj = 0; jj < OUT_F / 2; jj++) {
            float lo, hi;
            asm("mov.b64 {%0, %1}, %2;" : "=f"(lo), "=f"(hi) : "l"(a1[jj]));
            s1 += lo * sws[2 * jj] + hi * sws[2 * jj + 1];
            s2 += lo * swd[2 * jj] + hi * swd[2 * jj + 1];
            __half2 h2 = __floats2half2_rn(lo, hi);
            hh[jj] = *(unsigned*)&h2;
        }
        uint4* hr = (uint4*)(g_hh + (size_t)n1 * OUT_F);
#pragma unroll
        for (int i = 0; i < 6; i++)
            hr[i] = make_uint4(hh[4 * i], hh[4 * i + 1], hh[4 * i + 2], hh[4 * i + 3]);
        g_ssrc[n1] = s1;
        g_sdst[n1] = s2;
    }
}

// ---------------------------------------------------------------------------
// Single-pass exclusive scan of g_cnt -> g_off (decoupled lookback).
// ---------------------------------------------------------------------------
__global__ void __launch_bounds__(1024) k_scan()
{
    __shared__ int wsum[32];
    __shared__ int s_prefix;
    int tid = threadIdx.x, bid = blockIdx.x;
    int gid = bid * 1024 + tid;
    int lane = tid & 31, wid = tid >> 5;
    int x = (gid < N_NODES) ? g_cnt[gid] : 0;
    int incl = x;
#pragma unroll
    for (int o = 1; o < 32; o <<= 1) {
        int y = __shfl_up_sync(0xFFFFFFFFu, incl, o);
        if (lane >= o) incl += y;
    }
    if (lane == 31) wsum[wid] = incl;
    __syncthreads();
    if (wid == 0) {
        int v = wsum[lane];
#pragma unroll
        for (int o = 1; o < 32; o <<= 1) {
            int y = __shfl_up_sync(0xFFFFFFFFu, v, o);
            if (lane >= o) v += y;
        }
        wsum[lane] = v;
    }
    __syncthreads();
    int wofs = (wid > 0) ? wsum[wid - 1] : 0;
    int total = wsum[31];

    if (tid == 0) {
        if (bid == 0) {
            atomicExch(&g_state[0], (2ULL << 62) | (unsigned)total);
            s_prefix = 0;
        } else {
            atomicExch(&g_state[bid], (1ULL << 62) | (unsigned)total);
            int run = 0;
            int j = bid - 1;
            while (true) {
                unsigned long long v = atomicAdd(&g_state[j], 0ULL);
                unsigned f = (unsigned)(v >> 62);
                if (f == 0) { __nanosleep(20); continue; }
                run += (int)(v & 0xFFFFFFFFULL);
                if (f == 2) break;
                j--;
            }
            atomicExch(&g_state[bid], (2ULL << 62) | (unsigned)(run + total));
            s_prefix = run;
        }
    }
    __syncthreads();
    if (gid < N_NODES) g_off[gid] = s_prefix + wofs + incl - x;
}

// ---------------------------------------------------------------------------
// Scatter (atomic-free): pos = off[dst] + rank; ex = exp(leaky(...)).
// ---------------------------------------------------------------------------
__global__ void k_scatter(const int* __restrict__ src, const int* __restrict__ dst,
                          const float* __restrict__ attnb)
{
    int e = blockIdx.x * blockDim.x + threadIdx.x;
    if (e >= N_EDGES) return;
    int s = src[e], d = dst[e];
    float v = g_ssrc[s] + g_sdst[d] + attnb[0];
    v = (v > 0.0f) ? v : 0.2f * v;
    float ex = __expf(v);
    int pos = g_off[d] + g_rank[e];
    unsigned long long p =
        ((unsigned long long)(unsigned)s << 32) | (unsigned long long)__float_as_uint(ex);
    g_edge[pos] = p;
}

// ---------------------------------------------------------------------------
// Gather: 8 threads/node, 6 outputs each (3x u32 fp16 pairs per edge) --
// the best-known R3 structure -- with a 4-edge contiguous unroll for MLP.
// ---------------------------------------------------------------------------
__device__ __forceinline__ void acc6(float* a, unsigned w0, unsigned w1, unsigned w2, float ex)
{
    float2 f;
    f = __half22float2(*(__half2*)&w0); a[0] = fmaf(f.x, ex, a[0]); a[1] = fmaf(f.y, ex, a[1]);
    f = __half22float2(*(__half2*)&w1); a[2] = fmaf(f.x, ex, a[2]); a[3] = fmaf(f.y, ex, a[3]);
    f = __half22float2(*(__half2*)&w2); a[4] = fmaf(f.x, ex, a[4]); a[5] = fmaf(f.y, ex, a[5]);
}

__global__ void __launch_bounds__(256) k_gather(float* __restrict__ out)
{
    int gt = blockIdx.x * blockDim.x + threadIdx.x;
    int n = gt >> 3;
    int t = gt & 7;
    if (n >= N_NODES) return;
    int start = g_off[n];
    int deg = g_cnt[n];

    const unsigned* H = (const unsigned*)g_hh;  // row = 24 u32 (96B)
    int hb = t * 3;

    float a[6] = {0.f, 0.f, 0.f, 0.f, 0.f, 0.f};
    float den = 0.0f;

    int k = 0;
    for (; k + 4 <= deg; k += 4) {
        unsigned long long p0 = g_edge[start + k];
        unsigned long long p1 = g_edge[start + k + 1];
        unsigned long long p2 = g_edge[start + k + 2];
        unsigned long long p3 = g_edge[start + k + 3];
        float ex0 = __uint_as_float((unsigned)p0);
        float ex1 = __uint_as_float((unsigned)p1);
        float ex2 = __uint_as_float((unsigned)p2);
        float ex3 = __uint_as_float((unsigned)p3);
        int s0 = (int)(p0 >> 32), s1 = (int)(p1 >> 32);
        int s2 = (int)(p2 >> 32), s3 = (int)(p3 >> 32);
        const unsigned* h0 = H + s0 * 24 + hb;
        const unsigned* h1 = H + s1 * 24 + hb;
        const unsigned* h2 = H + s2 * 24 + hb;
        const unsigned* h3 = H + s3 * 24 + hb;
        unsigned w00 = h0[0], w01 = h0[1], w02 = h0[2];
        unsigned w10 = h1[0], w11 = h1[1], w12 = h1[2];
        unsigned w20 = h2[0], w21 = h2[1], w22 = h2[2];
        unsigned w30 = h3[0], w31 = h3[1], w32 = h3[2];
        den += (ex0 + ex1) + (ex2 + ex3);
        acc6(a, w00, w01, w02, ex0);
        acc6(a, w10, w11, w12, ex1);
        acc6(a, w20, w21, w22, ex2);
        acc6(a, w30, w31, w32, ex3);
    }
    for (; k < deg; k++) {
        unsigned long long p0 = g_edge[start + k];
        float ex0 = __uint_as_float((unsigned)p0);
        int s0 = (int)(p0 >> 32);
        const unsigned* h0 = H + s0 * 24 + hb;
        unsigned w00 = h0[0], w01 = h0[1], w02 = h0[2];
        den += ex0;
        acc6(a, w00, w01, w02, ex0);
    }

    float inv = (deg > 0) ? 1.0f / den : 0.0f;
    float2* op = (float2*)(out + (size_t)n * OUT_F + t * 6);
    op[0] = make_float2(a[0] * inv, a[1] * inv);
    op[1] = make_float2(a[2] * inv, a[3] * inv);
    op[2] = make_float2(a[4] * inv, a[5] * inv);

    // Restore zero-invariants for the next graph replay (warp-safe: the
    // g_cnt load above is issued for the whole warp before any lane stores).
    if (t == 0) g_cnt[n] = 0;
    if (t == 1 && n < NBLK_SCAN) g_state[n] = 0ULL;
}

// ---------------------------------------------------------------------------
extern "C" void kernel_launch(void* const* d_in, const int* in_sizes, int n_in,
                              void* d_out, int out_size)
{
    const float* feat  = (const float*)d_in[0];
    const float* Ww    = (const float*)d_in[1];
    const float* Wb    = (const float*)d_in[2];
    const float* attnw = (const float*)d_in[3];
    const float* attnb = (const float*)d_in[4];
    const int*   src   = (const int*)d_in[5];
    const int*   dst   = (const int*)d_in[6];
    float* out = (float*)d_out;

    k_gemm<<<(N_NODES + 255) / 256, 128>>>(feat, Ww, Wb, attnw, dst);
    k_scan<<<NBLK_SCAN, 1024>>>();
    k_scatter<<<(N_EDGES + 255) / 256, 256>>>(src, dst, attnb);
    k_gather<<<(N_NODES * 8 + 255) / 256, 256>>>(out);
}

// round 9
// speedup vs baseline: 1.0977x; 1.0977x over previous
#include <cuda_runtime.h>
#include <cuda_fp16.h>
#include <cuda_bf16.h>

#define N_NODES 100000
#define N_EDGES 1600000
#define IN_F 128
#define OUT_F 48
#define H_PAD 64   // fp16 elems per padded h row (128 bytes = 1 cache line)
#define NBLK_SCAN ((N_NODES + 1023) / 1024)   // 98

// Scratch (__device__ globals; zero-initialized at load; no allocations allowed)
__device__ float  g_ssrc[N_NODES];                    // h . w_src
__device__ float  g_sdst[N_NODES];                    // h . w_dst
__device__ __half g_hh[(size_t)N_NODES * H_PAD];      // projected features (fp16, 128B rows)
__device__ int    g_cnt[N_NODES];                     // degree by dst (zero at entry!)
__device__ int    g_off[N_NODES];                     // CSR offsets
__device__ int    g_cursor[N_NODES];                  // scatter cursors
__device__ unsigned long long g_state[NBLK_SCAN];     // lookback state (zero at entry!)
__device__ unsigned long long g_edge[N_EDGES];        // packed {src, ex}

// ---------------------------------------------------------------------------
// GEMM + dst histogram (fire-and-forget REDG atomics, hidden under FMA wall).
// ---------------------------------------------------------------------------
__global__ void __launch_bounds__(128) k_gemm(
    const float* __restrict__ feat, const float* __restrict__ Ww,
    const float* __restrict__ Wb, const float* __restrict__ attnw,
    const int* __restrict__ dst)
{
    {
        int gsz = gridDim.x * 128;
        for (int e = blockIdx.x * 128 + threadIdx.x; e < N_EDGES; e += gsz)
            atomicAdd(&g_cnt[dst[e]], 1);
    }

    __shared__ unsigned long long sWp[IN_F][OUT_F / 2];
    __shared__ float sb[OUT_F], sws[OUT_F], swd[OUT_F];

    int tid = threadIdx.x;
    for (int i = tid; i < IN_F * (OUT_F / 2); i += 128) {
        int k  = i / (OUT_F / 2);
        int jj = i % (OUT_F / 2);
        float lo = Ww[(2 * jj) * IN_F + k];
        float hi = Ww[(2 * jj + 1) * IN_F + k];
        unsigned long long p;
        asm("mov.b64 %0, {%1, %2};" : "=l"(p) : "f"(lo), "f"(hi));
        sWp[k][jj] = p;
    }
    if (tid < OUT_F) {
        sb[tid]  = Wb[tid];
        sws[tid] = attnw[tid];
        swd[tid] = attnw[OUT_F + tid];
    }
    __syncthreads();

    long n0 = (long)blockIdx.x * 256 + tid;
    long n1 = n0 + 128;
    bool v0 = n0 < N_NODES, v1 = n1 < N_NODES;
    const float4* r0 = (const float4*)(feat + (v0 ? n0 : 0) * IN_F);
    const float4* r1 = (const float4*)(feat + (v1 ? n1 : 0) * IN_F);

    unsigned long long a0[OUT_F / 2], a1[OUT_F / 2];
#pragma unroll
    for (int jj = 0; jj < OUT_F / 2; jj++) {
        unsigned long long p;
        asm("mov.b64 %0, {%1, %2};" : "=l"(p) : "f"(sb[2 * jj]), "f"(sb[2 * jj + 1]));
        a0[jj] = p;
        a1[jj] = p;
    }

#pragma unroll 2
    for (int k4 = 0; k4 < IN_F / 4; k4++) {
        float4 f0 = r0[k4];
        float4 f1 = r1[k4];
        float fs0[4] = {f0.x, f0.y, f0.z, f0.w};
        float fs1[4] = {f1.x, f1.y, f1.z, f1.w};
#pragma unroll
        for (int u = 0; u < 4; u++) {
            unsigned long long ff0, ff1;
            asm("mov.b64 %0, {%1, %1};" : "=l"(ff0) : "f"(fs0[u]));
            asm("mov.b64 %0, {%1, %1};" : "=l"(ff1) : "f"(fs1[u]));
            int k = 4 * k4 + u;
#pragma unroll
            for (int jj = 0; jj < OUT_F / 2; jj++) {
                unsigned long long w = sWp[k][jj];
                asm("fma.rn.f32x2 %0, %1, %2, %0;" : "+l"(a0[jj]) : "l"(ff0), "l"(w));
                asm("fma.rn.f32x2 %0, %1, %2, %0;" : "+l"(a1[jj]) : "l"(ff1), "l"(w));
            }
        }
    }

    if (v0) {
        float s1 = 0.0f, s2 = 0.0f;
        unsigned hh[OUT_F / 2];
#pragma unroll
        for (int jj = 0; jj < OUT_F / 2; jj++) {
            float lo, hi;
            asm("mov.b64 {%0, %1}, %2;" : "=f"(lo), "=f"(hi) : "l"(a0[jj]));
            s1 += lo * sws[2 * jj] + hi * sws[2 * jj + 1];
            s2 += lo * swd[2 * jj] + hi * swd[2 * jj + 1];
            __half2 h2 = __floats2half2_rn(lo, hi);
            hh[jj] = *(unsigned*)&h2;
        }
        uint4* hr = (uint4*)(g_hh + (size_t)n0 * H_PAD);
#pragma unroll
        for (int i = 0; i < 6; i++)
            hr[i] = make_uint4(hh[4 * i], hh[4 * i + 1], hh[4 * i + 2], hh[4 * i + 3]);
        hr[6] = make_uint4(0, 0, 0, 0);
        hr[7] = make_uint4(0, 0, 0, 0);
        g_ssrc[n0] = s1;
        g_sdst[n0] = s2;
    }
    if (v1) {
        float s1 = 0.0f, s2 = 0.0f;
        unsigned hh[OUT_F / 2];
#pragma unroll
        for (int jj = 0; jj < OUT_F / 2; jj++) {
            float lo, hi;
            asm("mov.b64 {%0, %1}, %2;" : "=f"(lo), "=f"(hi) : "l"(a1[jj]));
            s1 += lo * sws[2 * jj] + hi * sws[2 * jj + 1];
            s2 += lo * swd[2 * jj] + hi * swd[2 * jj + 1];
            __half2 h2 = __floats2half2_rn(lo, hi);
            hh[jj] = *(unsigned*)&h2;
        }
        uint4* hr = (uint4*)(g_hh + (size_t)n1 * H_PAD);
#pragma unroll
        for (int i = 0; i < 6; i++)
            hr[i] = make_uint4(hh[4 * i], hh[4 * i + 1], hh[4 * i + 2], hh[4 * i + 3]);
        hr[6] = make_uint4(0, 0, 0, 0);
        hr[7] = make_uint4(0, 0, 0, 0);
        g_ssrc[n1] = s1;
        g_sdst[n1] = s2;
    }
}

// ---------------------------------------------------------------------------
// Single-pass exclusive scan of g_cnt -> g_off/g_cursor (decoupled lookback).
// ---------------------------------------------------------------------------
__global__ void __launch_bounds__(1024) k_scan()
{
    __shared__ int wsum[32];
    __shared__ int s_prefix;
    int tid = threadIdx.x, bid = blockIdx.x;
    int gid = bid * 1024 + tid;
    int lane = tid & 31, wid = tid >> 5;
    int x = (gid < N_NODES) ? g_cnt[gid] : 0;
    int incl = x;
#pragma unroll
    for (int o = 1; o < 32; o <<= 1) {
        int y = __shfl_up_sync(0xFFFFFFFFu, incl, o);
        if (lane >= o) incl += y;
    }
    if (lane == 31) wsum[wid] = incl;
    __syncthreads();
    if (wid == 0) {
        int v = wsum[lane];
#pragma unroll
        for (int o = 1; o < 32; o <<= 1) {
            int y = __shfl_up_sync(0xFFFFFFFFu, v, o);
            if (lane >= o) v += y;
        }
        wsum[lane] = v;
    }
    __syncthreads();
    int wofs = (wid > 0) ? wsum[wid - 1] : 0;
    int total = wsum[31];

    if (tid == 0) {
        if (bid == 0) {
            atomicExch(&g_state[0], (2ULL << 62) | (unsigned)total);
            s_prefix = 0;
        } else {
            atomicExch(&g_state[bid], (1ULL << 62) | (unsigned)total);
            int run = 0;
            int j = bid - 1;
            while (true) {
                unsigned long long v = atomicAdd(&g_state[j], 0ULL);
                unsigned f = (unsigned)(v >> 62);
                if (f == 0) { __nanosleep(20); continue; }
                run += (int)(v & 0xFFFFFFFFULL);
                if (f == 2) break;
                j--;
            }
            atomicExch(&g_state[bid], (2ULL << 62) | (unsigned)(run + total));
            s_prefix = run;
        }
    }
    __syncthreads();
    if (gid < N_NODES) {
        int o = s_prefix + wofs + incl - x;
        g_off[gid] = o;
        g_cursor[gid] = o;
    }
}

// ---------------------------------------------------------------------------
// Scatter: ex = exp(leaky(s_src[s]+s_dst[d]+b)); place {src,ex} dst-sorted.
// (1 edge/thread, separate cursor array: the known-good R3 configuration.)
// ---------------------------------------------------------------------------
__global__ void k_scatter(const int* __restrict__ src, const int* __restrict__ dst,
                          const float* __restrict__ attnb)
{
    int e = blockIdx.x * blockDim.x + threadIdx.x;
    if (e >= N_EDGES) return;
    int s = src[e], d = dst[e];
    float v = g_ssrc[s] + g_sdst[d] + attnb[0];
    v = (v > 0.0f) ? v : 0.2f * v;
    float ex = __expf(v);
    int pos = atomicAdd(&g_cursor[d], 1);
    unsigned long long p =
        ((unsigned long long)(unsigned)s << 32) | (unsigned long long)__float_as_uint(ex);
    g_edge[pos] = p;
}

// ---------------------------------------------------------------------------
// Gather: 8 threads/node, padded 128B h rows, ONE LDG.128 per lane per edge
// (group collectively covers the whole cache line), contiguous 2-edge unroll
// -- the untried low-register / low-wavefront / high-occupancy cell.
// Lanes 0-5 own 8 outputs each; lanes 6-7 accumulate pad zeros + restores.
// ---------------------------------------------------------------------------
__device__ __forceinline__ void acc8(float* a, uint4 w, float ex)
{
    float2 f;
    f = __half22float2(*(__half2*)&w.x); a[0] = fmaf(f.x, ex, a[0]); a[1] = fmaf(f.y, ex, a[1]);
    f = __half22float2(*(__half2*)&w.y); a[2] = fmaf(f.x, ex, a[2]); a[3] = fmaf(f.y, ex, a[3]);
    f = __half22float2(*(__half2*)&w.z); a[4] = fmaf(f.x, ex, a[4]); a[5] = fmaf(f.y, ex, a[5]);
    f = __half22float2(*(__half2*)&w.w); a[6] = fmaf(f.x, ex, a[6]); a[7] = fmaf(f.y, ex, a[7]);
}

__global__ void __launch_bounds__(256) k_gather(float* __restrict__ out)
{
    int gt = blockIdx.x * blockDim.x + threadIdx.x;
    int n = gt >> 3;
    int t = gt & 7;
    if (n >= N_NODES) return;
    int start = g_off[n];
    int deg = g_cnt[n];

    const uint4* H = (const uint4*)g_hh;  // padded row = 8 uint4 (128B)

    float acc[8];
#pragma unroll
    for (int i = 0; i < 8; i++) acc[i] = 0.0f;
    float den = 0.0f;

    int k = 0;
    for (; k + 2 <= deg; k += 2) {
        unsigned long long p0 = g_edge[start + k];
        unsigned long long p1 = g_edge[start + k + 1];
        float ex0 = __uint_as_float((unsigned)p0);
        float ex1 = __uint_as_float((unsigned)p1);
        int s0 = (int)(p0 >> 32), s1 = (int)(p1 >> 32);
        uint4 w0 = H[s0 * 8 + t];
        uint4 w1 = H[s1 * 8 + t];
        den += ex0 + ex1;
        acc8(acc, w0, ex0);
        acc8(acc, w1, ex1);
    }
    if (k < deg) {
        unsigned long long p0 = g_edge[start + k];
        float ex0 = __uint_as_float((unsigned)p0);
        int s0 = (int)(p0 >> 32);
        uint4 w0 = H[s0 * 8 + t];
        den += ex0;
        acc8(acc, w0, ex0);
    }

    if (t < 6) {
        float inv = (deg > 0) ? 1.0f / den : 0.0f;
        float4* op = (float4*)(out + (size_t)n * OUT_F + t * 8);
        op[0] = make_float4(acc[0] * inv, acc[1] * inv, acc[2] * inv, acc[3] * inv);
        op[1] = make_float4(acc[4] * inv, acc[5] * inv, acc[6] * inv, acc[7] * inv);
    }
    // Restore zero-invariants for the next graph replay (warp-safe: the
    // g_cnt load above is issued for the whole warp before any lane stores).
    if (t == 6) g_cnt[n] = 0;
    if (t == 7 && n < NBLK_SCAN) g_state[n] = 0ULL;
}

// ---------------------------------------------------------------------------
extern "C" void kernel_launch(void* const* d_in, const int* in_sizes, int n_in,
                              void* d_out, int out_size)
{
    const float* feat  = (const float*)d_in[0];
    const float* Ww    = (const float*)d_in[1];
    const float* Wb    = (const float*)d_in[2];
    const float* attnw = (const float*)d_in[3];
    const float* attnb = (const float*)d_in[4];
    const int*   src   = (const int*)d_in[5];
    const int*   dst   = (const int*)d_in[6];
    float* out = (float*)d_out;

    k_gemm<<<(N_NODES + 255) / 256, 128>>>(feat, Ww, Wb, attnw, dst);
    k_scan<<<NBLK_SCAN, 1024>>>();
    k_scatter<<<(N_EDGES + 255) / 256, 256>>>(src, dst, attnb);
    k_gather<<<(N_NODES * 8 + 255) / 256, 256>>>(out);
}

// round 10
// speedup vs baseline: 1.1133x; 1.0143x over previous
#include <cuda_runtime.h>
#include <cuda_fp16.h>
#include <cuda_bf16.h>

#define N_NODES 100000
#define N_EDGES 1600000
#define IN_F 128
#define OUT_F 48
#define NBLK_SCAN ((N_NODES + 1023) / 1024)   // 98

// Scratch (__device__ globals; zero-initialized at load; no allocations allowed)
__device__ float  g_ssrc[N_NODES];                    // h . w_src
__device__ float  g_sdst[N_NODES];                    // h . w_dst
__device__ __half g_hh[(size_t)N_NODES * OUT_F];      // projected features (fp16, 96B rows)
__device__ int    g_cnt[N_NODES];                     // degree by dst (zero at entry!)
__device__ int    g_off[N_NODES];                     // CSR offsets
__device__ int    g_cursor[N_NODES];                  // scatter cursors
__device__ unsigned long long g_state[NBLK_SCAN];     // lookback state (zero at entry!)
__device__ unsigned long long g_edge[N_EDGES];        // packed {src, ex}

// ---------------------------------------------------------------------------
// Histogram of dst (launch #1). Fire-and-forget REDG atomics.
// ---------------------------------------------------------------------------
__global__ void k_hist(const int* __restrict__ dst)
{
    int e = blockIdx.x * blockDim.x + threadIdx.x;
    if (e < N_EDGES) atomicAdd(&g_cnt[dst[e]], 1);
}

// ---------------------------------------------------------------------------
// GEMM (launch #2): h = feat @ W^T + b (fp32 accum, fp16 store);
// s_src = h.w_src; s_dst = h.w_dst.
// ---------------------------------------------------------------------------
__global__ void __launch_bounds__(128) k_gemm(
    const float* __restrict__ feat, const float* __restrict__ Ww,
    const float* __restrict__ Wb, const float* __restrict__ attnw)
{
    __shared__ unsigned long long sWp[IN_F][OUT_F / 2];
    __shared__ float sb[OUT_F], sws[OUT_F], swd[OUT_F];

    int tid = threadIdx.x;
    for (int i = tid; i < IN_F * (OUT_F / 2); i += 128) {
        int k  = i / (OUT_F / 2);
        int jj = i % (OUT_F / 2);
        float lo = Ww[(2 * jj) * IN_F + k];
        float hi = Ww[(2 * jj + 1) * IN_F + k];
        unsigned long long p;
        asm("mov.b64 %0, {%1, %2};" : "=l"(p) : "f"(lo), "f"(hi));
        sWp[k][jj] = p;
    }
    if (tid < OUT_F) {
        sb[tid]  = Wb[tid];
        sws[tid] = attnw[tid];
        swd[tid] = attnw[OUT_F + tid];
    }
    __syncthreads();

    long n0 = (long)blockIdx.x * 256 + tid;
    long n1 = n0 + 128;
    bool v0 = n0 < N_NODES, v1 = n1 < N_NODES;
    const float4* r0 = (const float4*)(feat + (v0 ? n0 : 0) * IN_F);
    const float4* r1 = (const float4*)(feat + (v1 ? n1 : 0) * IN_F);

    unsigned long long a0[OUT_F / 2], a1[OUT_F / 2];
#pragma unroll
    for (int jj = 0; jj < OUT_F / 2; jj++) {
        unsigned long long p;
        asm("mov.b64 %0, {%1, %2};" : "=l"(p) : "f"(sb[2 * jj]), "f"(sb[2 * jj + 1]));
        a0[jj] = p;
        a1[jj] = p;
    }

#pragma unroll 2
    for (int k4 = 0; k4 < IN_F / 4; k4++) {
        float4 f0 = r0[k4];
        float4 f1 = r1[k4];
        float fs0[4] = {f0.x, f0.y, f0.z, f0.w};
        float fs1[4] = {f1.x, f1.y, f1.z, f1.w};
#pragma unroll
        for (int u = 0; u < 4; u++) {
            unsigned long long ff0, ff1;
            asm("mov.b64 %0, {%1, %1};" : "=l"(ff0) : "f"(fs0[u]));
            asm("mov.b64 %0, {%1, %1};" : "=l"(ff1) : "f"(fs1[u]));
            int k = 4 * k4 + u;
#pragma unroll
            for (int jj = 0; jj < OUT_F / 2; jj++) {
                unsigned long long w = sWp[k][jj];
                asm("fma.rn.f32x2 %0, %1, %2, %0;" : "+l"(a0[jj]) : "l"(ff0), "l"(w));
                asm("fma.rn.f32x2 %0, %1, %2, %0;" : "+l"(a1[jj]) : "l"(ff1), "l"(w));
            }
        }
    }

    if (v0) {
        float s1 = 0.0f, s2 = 0.0f;
        unsigned hh[OUT_F / 2];
#pragma unroll
        for (int jj = 0; jj < OUT_F / 2; jj++) {
            float lo, hi;
            asm("mov.b64 {%0, %1}, %2;" : "=f"(lo), "=f"(hi) : "l"(a0[jj]));
            s1 += lo * sws[2 * jj] + hi * sws[2 * jj + 1];
            s2 += lo * swd[2 * jj] + hi * swd[2 * jj + 1];
            __half2 h2 = __floats2half2_rn(lo, hi);
            hh[jj] = *(unsigned*)&h2;
        }
        uint4* hr = (uint4*)(g_hh + (size_t)n0 * OUT_F);
#pragma unroll
        for (int i = 0; i < 6; i++)
            hr[i] = make_uint4(hh[4 * i], hh[4 * i + 1], hh[4 * i + 2], hh[4 * i + 3]);
        g_ssrc[n0] = s1;
        g_sdst[n0] = s2;
    }
    if (v1) {
        float s1 = 0.0f, s2 = 0.0f;
        unsigned hh[OUT_F / 2];
#pragma unroll
        for (int jj = 0; jj < OUT_F / 2; jj++) {
            float lo, hi;
            asm("mov.b64 {%0, %1}, %2;" : "=f"(lo), "=f"(hi) : "l"(a1[jj]));
            s1 += lo * sws[2 * jj] + hi * sws[2 * jj + 1];
            s2 += lo * swd[2 * jj] + hi * swd[2 * jj + 1];
            __half2 h2 = __floats2half2_rn(lo, hi);
            hh[jj] = *(unsigned*)&h2;
        }
        uint4* hr = (uint4*)(g_hh + (size_t)n1 * OUT_F);
#pragma unroll
        for (int i = 0; i < 6; i++)
            hr[i] = make_uint4(hh[4 * i], hh[4 * i + 1], hh[4 * i + 2], hh[4 * i + 3]);
        g_ssrc[n1] = s1;
        g_sdst[n1] = s2;
    }
}

// ---------------------------------------------------------------------------
// Single-pass exclusive scan of g_cnt -> g_off/g_cursor (launch #3).
// ---------------------------------------------------------------------------
__global__ void __launch_bounds__(1024) k_scan()
{
    __shared__ int wsum[32];
    __shared__ int s_prefix;
    int tid = threadIdx.x, bid = blockIdx.x;
    int gid = bid * 1024 + tid;
    int lane = tid & 31, wid = tid >> 5;
    int x = (gid < N_NODES) ? g_cnt[gid] : 0;
    int incl = x;
#pragma unroll
    for (int o = 1; o < 32; o <<= 1) {
        int y = __shfl_up_sync(0xFFFFFFFFu, incl, o);
        if (lane >= o) incl += y;
    }
    if (lane == 31) wsum[wid] = incl;
    __syncthreads();
    if (wid == 0) {
        int v = wsum[lane];
#pragma unroll
        for (int o = 1; o < 32; o <<= 1) {
            int y = __shfl_up_sync(0xFFFFFFFFu, v, o);
            if (lane >= o) v += y;
        }
        wsum[lane] = v;
    }
    __syncthreads();
    int wofs = (wid > 0) ? wsum[wid - 1] : 0;
    int total = wsum[31];

    if (tid == 0) {
        if (bid == 0) {
            atomicExch(&g_state[0], (2ULL << 62) | (unsigned)total);
            s_prefix = 0;
        } else {
            atomicExch(&g_state[bid], (1ULL << 62) | (unsigned)total);
            int run = 0;
            int j = bid - 1;
            while (true) {
                unsigned long long v = atomicAdd(&g_state[j], 0ULL);
                unsigned f = (unsigned)(v >> 62);
                if (f == 0) { __nanosleep(20); continue; }
                run += (int)(v & 0xFFFFFFFFULL);
                if (f == 2) break;
                j--;
            }
            atomicExch(&g_state[bid], (2ULL << 62) | (unsigned)(run + total));
            s_prefix = run;
        }
    }
    __syncthreads();
    if (gid < N_NODES) {
        int o = s_prefix + wofs + incl - x;
        g_off[gid] = o;
        g_cursor[gid] = o;
    }
}

// ---------------------------------------------------------------------------
// Scatter (launch #4 -- profiled): ex = exp(leaky(s_src[s]+s_dst[d]+b));
// place {src,ex} at dst-sorted position.
// ---------------------------------------------------------------------------
__global__ void k_scatter(const int* __restrict__ src, const int* __restrict__ dst,
                          const float* __restrict__ attnb)
{
    int e = blockIdx.x * blockDim.x + threadIdx.x;
    if (e >= N_EDGES) return;
    int s = src[e], d = dst[e];
    float v = g_ssrc[s] + g_sdst[d] + attnb[0];
    v = (v > 0.0f) ? v : 0.2f * v;
    float ex = __expf(v);
    int pos = atomicAdd(&g_cursor[d], 1);
    unsigned long long p =
        ((unsigned long long)(unsigned)s << 32) | (unsigned long long)__float_as_uint(ex);
    g_edge[pos] = p;
}

// ---------------------------------------------------------------------------
// Gather (launch #5): EXACT best-known R3 configuration -- 8 threads/node,
// 6 outputs each (3x u32 fp16 pairs per edge), contiguous 2-edge unroll.
// ---------------------------------------------------------------------------
__device__ __forceinline__ void acc6(float* a, unsigned w0, unsigned w1, unsigned w2, float ex)
{
    float2 f;
    f = __half22float2(*(__half2*)&w0); a[0] = fmaf(f.x, ex, a[0]); a[1] = fmaf(f.y, ex, a[1]);
    f = __half22float2(*(__half2*)&w1); a[2] = fmaf(f.x, ex, a[2]); a[3] = fmaf(f.y, ex, a[3]);
    f = __half22float2(*(__half2*)&w2); a[4] = fmaf(f.x, ex, a[4]); a[5] = fmaf(f.y, ex, a[5]);
}

__global__ void __launch_bounds__(256) k_gather(float* __restrict__ out)
{
    int gt = blockIdx.x * blockDim.x + threadIdx.x;
    int n = gt >> 3;
    int t = gt & 7;
    if (n >= N_NODES) return;
    int start = g_off[n];
    int deg = g_cnt[n];

    const unsigned* H = (const unsigned*)g_hh;  // row = 24 u32 (96B)
    int hb = t * 3;

    float a0 = 0.f, a1 = 0.f, a2 = 0.f, a3 = 0.f, a4 = 0.f, a5 = 0.f, den = 0.f;

    int k = 0;
    for (; k + 2 <= deg; k += 2) {
        unsigned long long p0 = g_edge[start + k];
        unsigned long long p1 = g_edge[start + k + 1];
        float ex0 = __uint_as_float((unsigned)p0);
        float ex1 = __uint_as_float((unsigned)p1);
        int s0 = (int)(p0 >> 32), s1 = (int)(p1 >> 32);
        const unsigned* h0 = H + s0 * 24 + hb;
        const unsigned* h1 = H + s1 * 24 + hb;
        unsigned w00 = h0[0], w01 = h0[1], w02 = h0[2];
        unsigned w10 = h1[0], w11 = h1[1], w12 = h1[2];
        den += ex0 + ex1;
        float2 f;
        f = __half22float2(*(__half2*)&w00); a0 = fmaf(f.x, ex0, a0); a1 = fmaf(f.y, ex0, a1);
        f = __half22float2(*(__half2*)&w01); a2 = fmaf(f.x, ex0, a2); a3 = fmaf(f.y, ex0, a3);
        f = __half22float2(*(__half2*)&w02); a4 = fmaf(f.x, ex0, a4); a5 = fmaf(f.y, ex0, a5);
        f = __half22float2(*(__half2*)&w10); a0 = fmaf(f.x, ex1, a0); a1 = fmaf(f.y, ex1, a1);
        f = __half22float2(*(__half2*)&w11); a2 = fmaf(f.x, ex1, a2); a3 = fmaf(f.y, ex1, a3);
        f = __half22float2(*(__half2*)&w12); a4 = fmaf(f.x, ex1, a4); a5 = fmaf(f.y, ex1, a5);
    }
    if (k < deg) {
        unsigned long long p0 = g_edge[start + k];
        float ex0 = __uint_as_float((unsigned)p0);
        int s0 = (int)(p0 >> 32);
        const unsigned* h0 = H + s0 * 24 + hb;
        unsigned w00 = h0[0], w01 = h0[1], w02 = h0[2];
        den += ex0;
        float2 f;
        f = __half22float2(*(__half2*)&w00); a0 = fmaf(f.x, ex0, a0); a1 = fmaf(f.y, ex0, a1);
        f = __half22float2(*(__half2*)&w01); a2 = fmaf(f.x, ex0, a2); a3 = fmaf(f.y, ex0, a3);
        f = __half22float2(*(__half2*)&w02); a4 = fmaf(f.x, ex0, a4); a5 = fmaf(f.y, ex0, a5);
    }

    float inv = (deg > 0) ? 1.0f / den : 0.0f;
    float2* op = (float2*)(out + (size_t)n * OUT_F + t * 6);
    op[0] = make_float2(a0 * inv, a1 * inv);
    op[1] = make_float2(a2 * inv, a3 * inv);
    op[2] = make_float2(a4 * inv, a5 * inv);

    // Restore zero-invariants for the next graph replay (warp-safe: the
    // g_cnt load above is issued for the whole warp before any lane stores).
    if (t == 0) g_cnt[n] = 0;
    if (t == 1 && n < NBLK_SCAN) g_state[n] = 0ULL;
}

// ---------------------------------------------------------------------------
extern "C" void kernel_launch(void* const* d_in, const int* in_sizes, int n_in,
                              void* d_out, int out_size)
{
    const float* feat  = (const float*)d_in[0];
    const float* Ww    = (const float*)d_in[1];
    const float* Wb    = (const float*)d_in[2];
    const float* attnw = (const float*)d_in[3];
    const float* attnb = (const float*)d_in[4];
    const int*   src   = (const int*)d_in[5];
    const int*   dst   = (const int*)d_in[6];
    float* out = (float*)d_out;

    k_hist<<<(N_EDGES + 255) / 256, 256>>>(dst);                     // #1
    k_gemm<<<(N_NODES + 255) / 256, 128>>>(feat, Ww, Wb, attnw);     // #2
    k_scan<<<NBLK_SCAN, 1024>>>();                                   // #3
    k_scatter<<<(N_EDGES + 255) / 256, 256>>>(src, dst, attnb);      // #4 (profiled)
    k_gather<<<(N_NODES * 8 + 255) / 256, 256>>>(out);               // #5
}

// round 11
// speedup vs baseline: 1.1182x; 1.0043x over previous
#include <cuda_runtime.h>
#include <cuda_fp16.h>
#include <cuda_bf16.h>

#define N_NODES 100000
#define N_EDGES 1600000
#define IN_F 128
#define OUT_F 48
#define H_PAD 64   // fp16 elems per padded row (128B): 48 h + ssrc word + pad
#define NBLK_SCAN ((N_NODES + 1023) / 1024)   // 98

// Scratch (__device__ globals; zero-initialized at load; no allocations allowed)
__device__ float  g_ssrc[N_NODES];                    // h . w_src (for scatter-free logits)
__device__ float  g_sdst[N_NODES];                    // h . w_dst
__device__ __half g_hh[(size_t)N_NODES * H_PAD];      // 128B rows: h[48] | ssrc | pad
__device__ int    g_cnt[N_NODES];                     // degree by dst (zero at entry!)
__device__ int    g_off[N_NODES];                     // CSR offsets
__device__ int    g_cursor[N_NODES];                  // scatter cursors
__device__ unsigned long long g_state[NBLK_SCAN];     // lookback state (zero at entry!)
__device__ int    g_srt[N_EDGES];                     // dst-sorted src indices (4B/edge)

// ---------------------------------------------------------------------------
// GEMM + dst histogram (fire-and-forget REDG atomics under the FMA wall).
// h row layout (128B): words 0-23 = 48 fp16, word 24 = ssrc (f32 bits), pad.
// ---------------------------------------------------------------------------
__global__ void __launch_bounds__(128) k_gemm(
    const float* __restrict__ feat, const float* __restrict__ Ww,
    const float* __restrict__ Wb, const float* __restrict__ attnw,
    const int* __restrict__ dst)
{
    {
        int gsz = gridDim.x * 128;
        for (int e = blockIdx.x * 128 + threadIdx.x; e < N_EDGES; e += gsz)
            atomicAdd(&g_cnt[dst[e]], 1);
    }

    __shared__ unsigned long long sWp[IN_F][OUT_F / 2];
    __shared__ float sb[OUT_F], sws[OUT_F], swd[OUT_F];

    int tid = threadIdx.x;
    for (int i = tid; i < IN_F * (OUT_F / 2); i += 128) {
        int k  = i / (OUT_F / 2);
        int jj = i % (OUT_F / 2);
        float lo = Ww[(2 * jj) * IN_F + k];
        float hi = Ww[(2 * jj + 1) * IN_F + k];
        unsigned long long p;
        asm("mov.b64 %0, {%1, %2};" : "=l"(p) : "f"(lo), "f"(hi));
        sWp[k][jj] = p;
    }
    if (tid < OUT_F) {
        sb[tid]  = Wb[tid];
        sws[tid] = attnw[tid];
        swd[tid] = attnw[OUT_F + tid];
    }
    __syncthreads();

    long n0 = (long)blockIdx.x * 256 + tid;
    long n1 = n0 + 128;
    bool v0 = n0 < N_NODES, v1 = n1 < N_NODES;
    const float4* r0 = (const float4*)(feat + (v0 ? n0 : 0) * IN_F);
    const float4* r1 = (const float4*)(feat + (v1 ? n1 : 0) * IN_F);

    unsigned long long a0[OUT_F / 2], a1[OUT_F / 2];
#pragma unroll
    for (int jj = 0; jj < OUT_F / 2; jj++) {
        unsigned long long p;
        asm("mov.b64 %0, {%1, %2};" : "=l"(p) : "f"(sb[2 * jj]), "f"(sb[2 * jj + 1]));
        a0[jj] = p;
        a1[jj] = p;
    }

#pragma unroll 2
    for (int k4 = 0; k4 < IN_F / 4; k4++) {
        float4 f0 = r0[k4];
        float4 f1 = r1[k4];
        float fs0[4] = {f0.x, f0.y, f0.z, f0.w};
        float fs1[4] = {f1.x, f1.y, f1.z, f1.w};
#pragma unroll
        for (int u = 0; u < 4; u++) {
            unsigned long long ff0, ff1;
            asm("mov.b64 %0, {%1, %1};" : "=l"(ff0) : "f"(fs0[u]));
            asm("mov.b64 %0, {%1, %1};" : "=l"(ff1) : "f"(fs1[u]));
            int k = 4 * k4 + u;
#pragma unroll
            for (int jj = 0; jj < OUT_F / 2; jj++) {
                unsigned long long w = sWp[k][jj];
                asm("fma.rn.f32x2 %0, %1, %2, %0;" : "+l"(a0[jj]) : "l"(ff0), "l"(w));
                asm("fma.rn.f32x2 %0, %1, %2, %0;" : "+l"(a1[jj]) : "l"(ff1), "l"(w));
            }
        }
    }

    if (v0) {
        float s1 = 0.0f, s2 = 0.0f;
        unsigned hh[OUT_F / 2];
#pragma unroll
        for (int jj = 0; jj < OUT_F / 2; jj++) {
            float lo, hi;
            asm("mov.b64 {%0, %1}, %2;" : "=f"(lo), "=f"(hi) : "l"(a0[jj]));
            s1 += lo * sws[2 * jj] + hi * sws[2 * jj + 1];
            s2 += lo * swd[2 * jj] + hi * swd[2 * jj + 1];
            __half2 h2 = __floats2half2_rn(lo, hi);
            hh[jj] = *(unsigned*)&h2;
        }
        uint4* hr = (uint4*)(g_hh + (size_t)n0 * H_PAD);
#pragma unroll
        for (int i = 0; i < 6; i++)
            hr[i] = make_uint4(hh[4 * i], hh[4 * i + 1], hh[4 * i + 2], hh[4 * i + 3]);
        hr[6] = make_uint4(__float_as_uint(s1), 0, 0, 0);  // ssrc at word 24
        hr[7] = make_uint4(0, 0, 0, 0);
        g_ssrc[n0] = s1;
        g_sdst[n0] = s2;
    }
    if (v1) {
        float s1 = 0.0f, s2 = 0.0f;
        unsigned hh[OUT_F / 2];
#pragma unroll
        for (int jj = 0; jj < OUT_F / 2; jj++) {
            float lo, hi;
            asm("mov.b64 {%0, %1}, %2;" : "=f"(lo), "=f"(hi) : "l"(a1[jj]));
            s1 += lo * sws[2 * jj] + hi * sws[2 * jj + 1];
            s2 += lo * swd[2 * jj] + hi * swd[2 * jj + 1];
            __half2 h2 = __floats2half2_rn(lo, hi);
            hh[jj] = *(unsigned*)&h2;
        }
        uint4* hr = (uint4*)(g_hh + (size_t)n1 * H_PAD);
#pragma unroll
        for (int i = 0; i < 6; i++)
            hr[i] = make_uint4(hh[4 * i], hh[4 * i + 1], hh[4 * i + 2], hh[4 * i + 3]);
        hr[6] = make_uint4(__float_as_uint(s1), 0, 0, 0);
        hr[7] = make_uint4(0, 0, 0, 0);
        g_ssrc[n1] = s1;
        g_sdst[n1] = s2;
    }
}

// ---------------------------------------------------------------------------
// Single-pass exclusive scan of g_cnt -> g_off/g_cursor (decoupled lookback).
// ---------------------------------------------------------------------------
__global__ void __launch_bounds__(1024) k_scan()
{
    __shared__ int wsum[32];
    __shared__ int s_prefix;
    int tid = threadIdx.x, bid = blockIdx.x;
    int gid = bid * 1024 + tid;
    int lane = tid & 31, wid = tid >> 5;
    int x = (gid < N_NODES) ? g_cnt[gid] : 0;
    int incl = x;
#pragma unroll
    for (int o = 1; o < 32; o <<= 1) {
        int y = __shfl_up_sync(0xFFFFFFFFu, incl, o);
        if (lane >= o) incl += y;
    }
    if (lane == 31) wsum[wid] = incl;
    __syncthreads();
    if (wid == 0) {
        int v = wsum[lane];
#pragma unroll
        for (int o = 1; o < 32; o <<= 1) {
            int y = __shfl_up_sync(0xFFFFFFFFu, v, o);
            if (lane >= o) v += y;
        }
        wsum[lane] = v;
    }
    __syncthreads();
    int wofs = (wid > 0) ? wsum[wid - 1] : 0;
    int total = wsum[31];

    if (tid == 0) {
        if (bid == 0) {
            atomicExch(&g_state[0], (2ULL << 62) | (unsigned)total);
            s_prefix = 0;
        } else {
            atomicExch(&g_state[bid], (1ULL << 62) | (unsigned)total);
            int run = 0;
            int j = bid - 1;
            while (true) {
                unsigned long long v = atomicAdd(&g_state[j], 0ULL);
                unsigned f = (unsigned)(v >> 62);
                if (f == 0) { __nanosleep(20); continue; }
                run += (int)(v & 0xFFFFFFFFULL);
                if (f == 2) break;
                j--;
            }
            atomicExch(&g_state[bid], (2ULL << 62) | (unsigned)(run + total));
            s_prefix = run;
        }
    }
    __syncthreads();
    if (gid < N_NODES) {
        int o = s_prefix + wofs + incl - x;
        g_off[gid] = o;
        g_cursor[gid] = o;
    }
}

// ---------------------------------------------------------------------------
// Scatter-lite: sort src indices by dst. NO value computation, NO random
// gathers -- just 2 sequential loads, 1 cursor atomic, 1 random 4B store.
// ---------------------------------------------------------------------------
__global__ void k_scatter(const int* __restrict__ src, const int* __restrict__ dst)
{
    int e = blockIdx.x * blockDim.x + threadIdx.x;
    if (e >= N_EDGES) return;
    int s = src[e], d = dst[e];
    int pos = atomicAdd(&g_cursor[d], 1);
    g_srt[pos] = s;
}

// ---------------------------------------------------------------------------
// Gather: 8 threads/node, R3-winning shape (3x u32 h-words, 6 accumulators,
// contiguous 2-edge unroll). Computes the logit + exp in-kernel:
// sdst[n]+b loaded once per node; ssrc[s] rides in the h-row's cache line.
// ---------------------------------------------------------------------------
__global__ void __launch_bounds__(256) k_gather(float* __restrict__ out,
                                                const float* __restrict__ attnb)
{
    int gt = blockIdx.x * blockDim.x + threadIdx.x;
    int n = gt >> 3;
    int t = gt & 7;
    if (n >= N_NODES) return;
    int start = g_off[n];
    int deg = g_cnt[n];
    float sdn = g_sdst[n] + attnb[0];

    const unsigned* H = (const unsigned*)g_hh;  // row = 32 u32 (128B)
    int hb = t * 3;

    float a0 = 0.f, a1 = 0.f, a2 = 0.f, a3 = 0.f, a4 = 0.f, a5 = 0.f, den = 0.f;

    int k = 0;
    for (; k + 2 <= deg; k += 2) {
        int s0 = g_srt[start + k];
        int s1 = g_srt[start + k + 1];
        const unsigned* r0 = H + s0 * 32;
        const unsigned* r1 = H + s1 * 32;
        float sv0 = __uint_as_float(r0[24]);
        float sv1 = __uint_as_float(r1[24]);
        unsigned w00 = r0[hb], w01 = r0[hb + 1], w02 = r0[hb + 2];
        unsigned w10 = r1[hb], w11 = r1[hb + 1], w12 = r1[hb + 2];
        float v0 = sv0 + sdn;
        float v1 = sv1 + sdn;
        v0 = (v0 > 0.0f) ? v0 : 0.2f * v0;
        v1 = (v1 > 0.0f) ? v1 : 0.2f * v1;
        float ex0 = __expf(v0);
        float ex1 = __expf(v1);
        den += ex0 + ex1;
        float2 f;
        f = __half22float2(*(__half2*)&w00); a0 = fmaf(f.x, ex0, a0); a1 = fmaf(f.y, ex0, a1);
        f = __half22float2(*(__half2*)&w01); a2 = fmaf(f.x, ex0, a2); a3 = fmaf(f.y, ex0, a3);
        f = __half22float2(*(__half2*)&w02); a4 = fmaf(f.x, ex0, a4); a5 = fmaf(f.y, ex0, a5);
        f = __half22float2(*(__half2*)&w10); a0 = fmaf(f.x, ex1, a0); a1 = fmaf(f.y, ex1, a1);
        f = __half22float2(*(__half2*)&w11); a2 = fmaf(f.x, ex1, a2); a3 = fmaf(f.y, ex1, a3);
        f = __half22float2(*(__half2*)&w12); a4 = fmaf(f.x, ex1, a4); a5 = fmaf(f.y, ex1, a5);
    }
    if (k < deg) {
        int s0 = g_srt[start + k];
        const unsigned* r0 = H + s0 * 32;
        float sv0 = __uint_as_float(r0[24]);
        unsigned w00 = r0[hb], w01 = r0[hb + 1], w02 = r0[hb + 2];
        float v0 = sv0 + sdn;
        v0 = (v0 > 0.0f) ? v0 : 0.2f * v0;
        float ex0 = __expf(v0);
        den += ex0;
        float2 f;
        f = __half22float2(*(__half2*)&w00); a0 = fmaf(f.x, ex0, a0); a1 = fmaf(f.y, ex0, a1);
        f = __half22float2(*(__half2*)&w01); a2 = fmaf(f.x, ex0, a2); a3 = fmaf(f.y, ex0, a3);
        f = __half22float2(*(__half2*)&w02); a4 = fmaf(f.x, ex0, a4); a5 = fmaf(f.y, ex0, a5);
    }

    float inv = (deg > 0) ? 1.0f / den : 0.0f;
    float2* op = (float2*)(out + (size_t)n * OUT_F + t * 6);
    op[0] = make_float2(a0 * inv, a1 * inv);
    op[1] = make_float2(a2 * inv, a3 * inv);
    op[2] = make_float2(a4 * inv, a5 * inv);

    // Restore zero-invariants for the next graph replay (warp-safe: the
    // g_cnt load above is issued for the whole warp before any lane stores).
    if (t == 0) g_cnt[n] = 0;
    if (t == 1 && n < NBLK_SCAN) g_state[n] = 0ULL;
}

// ---------------------------------------------------------------------------
extern "C" void kernel_launch(void* const* d_in, const int* in_sizes, int n_in,
                              void* d_out, int out_size)
{
    const float* feat  = (const float*)d_in[0];
    const float* Ww    = (const float*)d_in[1];
    const float* Wb    = (const float*)d_in[2];
    const float* attnw = (const float*)d_in[3];
    const float* attnb = (const float*)d_in[4];
    const int*   src   = (const int*)d_in[5];
    const int*   dst   = (const int*)d_in[6];
    float* out = (float*)d_out;

    k_gemm<<<(N_NODES + 255) / 256, 128>>>(feat, Ww, Wb, attnw, dst);  // #1
    k_scan<<<NBLK_SCAN, 1024>>>();                                      // #2
    k_scatter<<<(N_EDGES + 255) / 256, 256>>>(src, dst);                // #3
    k_gather<<<(N_NODES * 8 + 255) / 256, 256>>>(out, attnb);           // #4 (profiled)
}

// round 12
// speedup vs baseline: 1.4420x; 1.2896x over previous
#include <cuda_runtime.h>
#include <cuda_fp16.h>

#define N_NODES 100000
#define N_EDGES 1600000
#define IN_F 128
#define OUT_F 48
#define ROWW 32    // u32 words per g_hh row (128B)
#define H_PAD 64   // fp16 elems per row
#define WSTR 136   // smem W stride in halves (bank-conflict-free)
#define NBLK_SCAN ((N_NODES + 1023) / 1024)   // 98

// Scratch (__device__ globals; zero-initialized at load; no allocations allowed)
__device__ float  g_sdst[N_NODES];                    // h . w_dst
__device__ __half g_hh[(size_t)N_NODES * H_PAD];      // 128B rows: h[48] | ssrc | pad
__device__ int    g_cnt[N_NODES];                     // degree by dst (zero at entry!)
__device__ int    g_off[N_NODES];                     // CSR offsets
__device__ int    g_cursor[N_NODES];                  // scatter cursors
__device__ unsigned long long g_state[NBLK_SCAN];     // lookback state (zero at entry!)
__device__ int    g_srt[N_EDGES];                     // dst-sorted src indices

__device__ __forceinline__ unsigned h2u(float x, float y)
{
    __half2 h = __floats2half2_rn(x, y);
    return *(unsigned*)&h;
}

__device__ __forceinline__ void mma16816(float* c, const unsigned* a, const unsigned* b)
{
    asm volatile(
        "mma.sync.aligned.m16n8k16.row.col.f32.f16.f16.f32 "
        "{%0,%1,%2,%3}, {%4,%5,%6,%7}, {%8,%9}, {%0,%1,%2,%3};"
        : "+f"(c[0]), "+f"(c[1]), "+f"(c[2]), "+f"(c[3])
        : "r"(a[0]), "r"(a[1]), "r"(a[2]), "r"(a[3]), "r"(b[0]), "r"(b[1]));
}

// ---------------------------------------------------------------------------
// Tensor-core GEMM + dst histogram.
// Block = 256 threads (8 warps); warp computes a 32-row strip x 48 cols.
// h row layout (128B): words 0-23 = 48 fp16, word 24 = ssrc (f32 bits).
// ---------------------------------------------------------------------------
__global__ void __launch_bounds__(256) k_gemm(
    const float* __restrict__ feat, const float* __restrict__ Ww,
    const float* __restrict__ Wb, const float* __restrict__ attnw,
    const int* __restrict__ dst)
{
    int tid = threadIdx.x;

    // --- histogram of dst (grid-stride; fire-and-forget REDG atomics) ---
    {
        int gsz = gridDim.x * 256;
        for (int e = blockIdx.x * 256 + tid; e < N_EDGES; e += gsz)
            atomicAdd(&g_cnt[dst[e]], 1);
    }

    __shared__ __half sW[OUT_F * WSTR];
    __shared__ float sws[OUT_F], swd[OUT_F], sb[OUT_F];

    for (int i = tid; i < OUT_F * IN_F; i += 256) {
        int n = i >> 7, k = i & 127;
        sW[n * WSTR + k] = __float2half_rn(Ww[n * IN_F + k]);
    }
    if (tid < OUT_F) {
        sb[tid]  = Wb[tid];
        sws[tid] = attnw[tid];
        swd[tid] = attnw[OUT_F + tid];
    }
    __syncthreads();

    int warp = tid >> 5, lane = tid & 31;
    int g = lane >> 2, tig = lane & 3;
    long m_warp = (long)blockIdx.x * 256 + warp * 32;
    if (m_warp >= N_NODES) return;

    float c[2][6][4];
#pragma unroll
    for (int mt = 0; mt < 2; mt++)
#pragma unroll
        for (int nt = 0; nt < 6; nt++)
#pragma unroll
            for (int i = 0; i < 4; i++) c[mt][nt][i] = 0.0f;

#pragma unroll 2
    for (int ks = 0; ks < 8; ks++) {
        int k0 = ks << 4;
        unsigned a[2][4];
#pragma unroll
        for (int mt = 0; mt < 2; mt++) {
            long r0 = m_warp + mt * 16 + g;
            long r1 = r0 + 8;
            if (r0 > N_NODES - 1) r0 = N_NODES - 1;
            if (r1 > N_NODES - 1) r1 = N_NODES - 1;
            const float2* p0 = (const float2*)(feat + (size_t)r0 * IN_F + k0) + tig;
            const float2* p1 = (const float2*)(feat + (size_t)r1 * IN_F + k0) + tig;
            float2 f00 = p0[0], f01 = p0[4];
            float2 f10 = p1[0], f11 = p1[4];
            a[mt][0] = h2u(f00.x, f00.y);
            a[mt][1] = h2u(f10.x, f10.y);
            a[mt][2] = h2u(f01.x, f01.y);
            a[mt][3] = h2u(f11.x, f11.y);
        }
        unsigned b[6][2];
#pragma unroll
        for (int nt = 0; nt < 6; nt++) {
            const __half* wp = sW + (nt * 8 + g) * WSTR + k0 + tig * 2;
            b[nt][0] = *(const unsigned*)wp;
            b[nt][1] = *(const unsigned*)(wp + 8);
        }
#pragma unroll
        for (int mt = 0; mt < 2; mt++)
#pragma unroll
            for (int nt = 0; nt < 6; nt++)
                mma16816(c[mt][nt], a[mt], b[nt]);
    }

    // --- epilogue: bias, s_src/s_dst (quad reduce), fp16 h + ssrc store ---
    float ws0[6], ws1[6], wd0[6], wd1[6], b0[6], b1[6];
#pragma unroll
    for (int nt = 0; nt < 6; nt++) {
        int col = nt * 8 + tig * 2;
        ws0[nt] = sws[col]; ws1[nt] = sws[col + 1];
        wd0[nt] = swd[col]; wd1[nt] = swd[col + 1];
        b0[nt]  = sb[col];  b1[nt]  = sb[col + 1];
    }

#pragma unroll
    for (int mt = 0; mt < 2; mt++) {
#pragma unroll
        for (int rr = 0; rr < 2; rr++) {
            float s1 = 0.0f, s2 = 0.0f;
            unsigned hh[6];
#pragma unroll
            for (int nt = 0; nt < 6; nt++) {
                float h0 = c[mt][nt][rr * 2]     + b0[nt];
                float h1 = c[mt][nt][rr * 2 + 1] + b1[nt];
                s1 = fmaf(h0, ws0[nt], fmaf(h1, ws1[nt], s1));
                s2 = fmaf(h0, wd0[nt], fmaf(h1, wd1[nt], s2));
                hh[nt] = h2u(h0, h1);
            }
            s1 += __shfl_xor_sync(0xFFFFFFFFu, s1, 1);
            s1 += __shfl_xor_sync(0xFFFFFFFFu, s1, 2);
            s2 += __shfl_xor_sync(0xFFFFFFFFu, s2, 1);
            s2 += __shfl_xor_sync(0xFFFFFFFFu, s2, 2);

            long row = m_warp + mt * 16 + rr * 8 + g;
            if (row < N_NODES) {
                unsigned* rp = (unsigned*)g_hh + (size_t)row * ROWW;
#pragma unroll
                for (int nt = 0; nt < 6; nt++)
                    rp[nt * 4 + tig] = hh[nt];
                if (tig == 0) {
                    ((float*)rp)[24] = s1;   // ssrc rides in the h cache line
                    g_sdst[row] = s2;
                }
            }
        }
    }
}

// ---------------------------------------------------------------------------
// Single-pass exclusive scan of g_cnt -> g_off/g_cursor (decoupled lookback).
// ---------------------------------------------------------------------------
__global__ void __launch_bounds__(1024) k_scan()
{
    __shared__ int wsum[32];
    __shared__ int s_prefix;
    int tid = threadIdx.x, bid = blockIdx.x;
    int gid = bid * 1024 + tid;
    int lane = tid & 31, wid = tid >> 5;
    int x = (gid < N_NODES) ? g_cnt[gid] : 0;
    int incl = x;
#pragma unroll
    for (int o = 1; o < 32; o <<= 1) {
        int y = __shfl_up_sync(0xFFFFFFFFu, incl, o);
        if (lane >= o) incl += y;
    }
    if (lane == 31) wsum[wid] = incl;
    __syncthreads();
    if (wid == 0) {
        int v = wsum[lane];
#pragma unroll
        for (int o = 1; o < 32; o <<= 1) {
            int y = __shfl_up_sync(0xFFFFFFFFu, v, o);
            if (lane >= o) v += y;
        }
        wsum[lane] = v;
    }
    __syncthreads();
    int wofs = (wid > 0) ? wsum[wid - 1] : 0;
    int total = wsum[31];

    if (tid == 0) {
        if (bid == 0) {
            atomicExch(&g_state[0], (2ULL << 62) | (unsigned)total);
            s_prefix = 0;
        } else {
            atomicExch(&g_state[bid], (1ULL << 62) | (unsigned)total);
            int run = 0;
            int j = bid - 1;
            while (true) {
                unsigned long long v = atomicAdd(&g_state[j], 0ULL);
                unsigned f = (unsigned)(v >> 62);
                if (f == 0) { __nanosleep(20); continue; }
                run += (int)(v & 0xFFFFFFFFULL);
                if (f == 2) break;
                j--;
            }
            atomicExch(&g_state[bid], (2ULL << 62) | (unsigned)(run + total));
            s_prefix = run;
        }
    }
    __syncthreads();
    if (gid < N_NODES) {
        int o = s_prefix + wofs + incl - x;
        g_off[gid] = o;
        g_cursor[gid] = o;
    }
}

// ---------------------------------------------------------------------------
// Scatter-lite: sort src indices by dst (2 sequential loads, 1 cursor atomic,
// 1 random 4B store).
// ---------------------------------------------------------------------------
__global__ void k_scatter(const int* __restrict__ src, const int* __restrict__ dst)
{
    int e = blockIdx.x * blockDim.x + threadIdx.x;
    if (e >= N_EDGES) return;
    int s = src[e], d = dst[e];
    int pos = atomicAdd(&g_cursor[d], 1);
    g_srt[pos] = s;
}

// ---------------------------------------------------------------------------
// Gather: 8 threads/node; logit+exp computed in-kernel (sdst[n]+b once per
// node; ssrc[s] rides in the h-row's cache line at word 24).
// ---------------------------------------------------------------------------
__global__ void __launch_bounds__(256) k_gather(float* __restrict__ out,
                                                const float* __restrict__ attnb)
{
    int gt = blockIdx.x * blockDim.x + threadIdx.x;
    int n = gt >> 3;
    int t = gt & 7;
    if (n >= N_NODES) return;
    int start = g_off[n];
    int deg = g_cnt[n];
    float sdn = g_sdst[n] + attnb[0];

    const unsigned* H = (const unsigned*)g_hh;  // row = 32 u32 (128B)
    int hb = t * 3;

    float a0 = 0.f, a1 = 0.f, a2 = 0.f, a3 = 0.f, a4 = 0.f, a5 = 0.f, den = 0.f;

    int k = 0;
    for (; k + 2 <= deg; k += 2) {
        int s0 = g_srt[start + k];
        int s1 = g_srt[start + k + 1];
        const unsigned* r0 = H + s0 * ROWW;
        const unsigned* r1 = H + s1 * ROWW;
        float sv0 = __uint_as_float(r0[24]);
        float sv1 = __uint_as_float(r1[24]);
        unsigned w00 = r0[hb], w01 = r0[hb + 1], w02 = r0[hb + 2];
        unsigned w10 = r1[hb], w11 = r1[hb + 1], w12 = r1[hb + 2];
        float v0 = sv0 + sdn;
        float v1 = sv1 + sdn;
        v0 = (v0 > 0.0f) ? v0 : 0.2f * v0;
        v1 = (v1 > 0.0f) ? v1 : 0.2f * v1;
        float ex0 = __expf(v0);
        float ex1 = __expf(v1);
        den += ex0 + ex1;
        float2 f;
        f = __half22float2(*(__half2*)&w00); a0 = fmaf(f.x, ex0, a0); a1 = fmaf(f.y, ex0, a1);
        f = __half22float2(*(__half2*)&w01); a2 = fmaf(f.x, ex0, a2); a3 = fmaf(f.y, ex0, a3);
        f = __half22float2(*(__half2*)&w02); a4 = fmaf(f.x, ex0, a4); a5 = fmaf(f.y, ex0, a5);
        f = __half22float2(*(__half2*)&w10); a0 = fmaf(f.x, ex1, a0); a1 = fmaf(f.y, ex1, a1);
        f = __half22float2(*(__half2*)&w11); a2 = fmaf(f.x, ex1, a2); a3 = fmaf(f.y, ex1, a3);
        f = __half22float2(*(__half2*)&w12); a4 = fmaf(f.x, ex1, a4); a5 = fmaf(f.y, ex1, a5);
    }
    if (k < deg) {
        int s0 = g_srt[start + k];
        const unsigned* r0 = H + s0 * ROWW;
        float sv0 = __uint_as_float(r0[24]);
        unsigned w00 = r0[hb], w01 = r0[hb + 1], w02 = r0[hb + 2];
        float v0 = sv0 + sdn;
        v0 = (v0 > 0.0f) ? v0 : 0.2f * v0;
        float ex0 = __expf(v0);
        den += ex0;
        float2 f;
        f = __half22float2(*(__half2*)&w00); a0 = fmaf(f.x, ex0, a0); a1 = fmaf(f.y, ex0, a1);
        f = __half22float2(*(__half2*)&w01); a2 = fmaf(f.x, ex0, a2); a3 = fmaf(f.y, ex0, a3);
        f = __half22float2(*(__half2*)&w02); a4 = fmaf(f.x, ex0, a4); a5 = fmaf(f.y, ex0, a5);
    }

    float inv = (deg > 0) ? 1.0f / den : 0.0f;
    float2* op = (float2*)(out + (size_t)n * OUT_F + t * 6);
    op[0] = make_float2(a0 * inv, a1 * inv);
    op[1] = make_float2(a2 * inv, a3 * inv);
    op[2] = make_float2(a4 * inv, a5 * inv);

    // Restore zero-invariants for the next graph replay (warp-safe: the
    // g_cnt load above is issued for the whole warp before any lane stores).
    if (t == 0) g_cnt[n] = 0;
    if (t == 1 && n < NBLK_SCAN) g_state[n] = 0ULL;
}

// ---------------------------------------------------------------------------
extern "C" void kernel_launch(void* const* d_in, const int* in_sizes, int n_in,
                              void* d_out, int out_size)
{
    const float* feat  = (const float*)d_in[0];
    const float* Ww    = (const float*)d_in[1];
    const float* Wb    = (const float*)d_in[2];
    const float* attnw = (const float*)d_in[3];
    const float* attnb = (const float*)d_in[4];
    const int*   src   = (const int*)d_in[5];
    const int*   dst   = (const int*)d_in[6];
    float* out = (float*)d_out;

    k_gemm<<<(N_NODES + 255) / 256, 256>>>(feat, Ww, Wb, attnw, dst);  // #1
    k_scan<<<NBLK_SCAN, 1024>>>();                                      // #2
    k_scatter<<<(N_EDGES + 255) / 256, 256>>>(src, dst);                // #3
    k_gather<<<(N_NODES * 8 + 255) / 256, 256>>>(out, attnb);           // #4 (profiled)
}

// round 13
// speedup vs baseline: 1.5373x; 1.0661x over previous
#include <cuda_runtime.h>
#include <cuda_fp16.h>

#define N_NODES 100000
#define N_EDGES 1600000
#define IN_F 128
#define OUT_F 48
#define ROWW 32    // u32 words per g_hh row (128B)
#define H_PAD 64   // fp16 elems per row
#define WSTR 136   // smem W stride in halves (bank-conflict-free)
#define NBLK_SCAN ((N_NODES + 1023) / 1024)   // 98

// Scratch (__device__ globals; zero-initialized at load; no allocations allowed)
__device__ float  g_sdst[N_NODES];                    // h . w_dst
__device__ __half g_hh[(size_t)N_NODES * H_PAD];      // 128B rows: h[48] | ssrc | pad
__device__ int    g_cnt[N_NODES];                     // degree by dst (zero at entry!)
__device__ int    g_off[N_NODES];                     // CSR offsets
__device__ int    g_cursor[N_NODES];                  // scatter cursors
__device__ unsigned long long g_state[NBLK_SCAN];     // lookback state (zero at entry!)
__device__ int    g_srt[N_EDGES];                     // dst-sorted src indices

__device__ __forceinline__ unsigned h2u(float x, float y)
{
    __half2 h = __floats2half2_rn(x, y);
    return *(unsigned*)&h;
}

__device__ __forceinline__ void mma16816(float* c, const unsigned* a, const unsigned* b)
{
    asm volatile(
        "mma.sync.aligned.m16n8k16.row.col.f32.f16.f16.f32 "
        "{%0,%1,%2,%3}, {%4,%5,%6,%7}, {%8,%9}, {%0,%1,%2,%3};"
        : "+f"(c[0]), "+f"(c[1]), "+f"(c[2]), "+f"(c[3])
        : "r"(a[0]), "r"(a[1]), "r"(a[2]), "r"(a[3]), "r"(b[0]), "r"(b[1]));
}

// ---------------------------------------------------------------------------
// Histogram of dst (branch A head). Fire-and-forget REDG atomics.
// ---------------------------------------------------------------------------
__global__ void k_hist(const int* __restrict__ dst)
{
    int e = blockIdx.x * blockDim.x + threadIdx.x;
    if (e < N_EDGES) atomicAdd(&g_cnt[dst[e]], 1);
}

// ---------------------------------------------------------------------------
// Tensor-core GEMM (branch B, runs concurrently with hist/scan/scatter).
// Block = 256 threads (8 warps); warp computes a 32-row strip x 48 cols.
// h row layout (128B): words 0-23 = 48 fp16, word 24 = ssrc (f32 bits).
// ---------------------------------------------------------------------------
__global__ void __launch_bounds__(256) k_gemm(
    const float* __restrict__ feat, const float* __restrict__ Ww,
    const float* __restrict__ Wb, const float* __restrict__ attnw)
{
    int tid = threadIdx.x;

    __shared__ __half sW[OUT_F * WSTR];
    __shared__ float sws[OUT_F], swd[OUT_F], sb[OUT_F];

    for (int i = tid; i < OUT_F * IN_F; i += 256) {
        int n = i >> 7, k = i & 127;
        sW[n * WSTR + k] = __float2half_rn(Ww[n * IN_F + k]);
    }
    if (tid < OUT_F) {
        sb[tid]  = Wb[tid];
        sws[tid] = attnw[tid];
        swd[tid] = attnw[OUT_F + tid];
    }
    __syncthreads();

    int warp = tid >> 5, lane = tid & 31;
    int g = lane >> 2, tig = lane & 3;
    long m_warp = (long)blockIdx.x * 256 + warp * 32;
    if (m_warp >= N_NODES) return;

    float c[2][6][4];
#pragma unroll
    for (int mt = 0; mt < 2; mt++)
#pragma unroll
        for (int nt = 0; nt < 6; nt++)
#pragma unroll
            for (int i = 0; i < 4; i++) c[mt][nt][i] = 0.0f;

#pragma unroll 2
    for (int ks = 0; ks < 8; ks++) {
        int k0 = ks << 4;
        unsigned a[2][4];
#pragma unroll
        for (int mt = 0; mt < 2; mt++) {
            long r0 = m_warp + mt * 16 + g;
            long r1 = r0 + 8;
            if (r0 > N_NODES - 1) r0 = N_NODES - 1;
            if (r1 > N_NODES - 1) r1 = N_NODES - 1;
            const float2* p0 = (const float2*)(feat + (size_t)r0 * IN_F + k0) + tig;
            const float2* p1 = (const float2*)(feat + (size_t)r1 * IN_F + k0) + tig;
            float2 f00 = p0[0], f01 = p0[4];
            float2 f10 = p1[0], f11 = p1[4];
            a[mt][0] = h2u(f00.x, f00.y);
            a[mt][1] = h2u(f10.x, f10.y);
            a[mt][2] = h2u(f01.x, f01.y);
            a[mt][3] = h2u(f11.x, f11.y);
        }
        unsigned b[6][2];
#pragma unroll
        for (int nt = 0; nt < 6; nt++) {
            const __half* wp = sW + (nt * 8 + g) * WSTR + k0 + tig * 2;
            b[nt][0] = *(const unsigned*)wp;
            b[nt][1] = *(const unsigned*)(wp + 8);
        }
#pragma unroll
        for (int mt = 0; mt < 2; mt++)
#pragma unroll
            for (int nt = 0; nt < 6; nt++)
                mma16816(c[mt][nt], a[mt], b[nt]);
    }

    // --- epilogue: bias, s_src/s_dst (quad reduce), fp16 h + ssrc store ---
    float ws0[6], ws1[6], wd0[6], wd1[6], b0[6], b1[6];
#pragma unroll
    for (int nt = 0; nt < 6; nt++) {
        int col = nt * 8 + tig * 2;
        ws0[nt] = sws[col]; ws1[nt] = sws[col + 1];
        wd0[nt] = swd[col]; wd1[nt] = swd[col + 1];
        b0[nt]  = sb[col];  b1[nt]  = sb[col + 1];
    }

#pragma unroll
    for (int mt = 0; mt < 2; mt++) {
#pragma unroll
        for (int rr = 0; rr < 2; rr++) {
            float s1 = 0.0f, s2 = 0.0f;
            unsigned hh[6];
#pragma unroll
            for (int nt = 0; nt < 6; nt++) {
                float h0 = c[mt][nt][rr * 2]     + b0[nt];
                float h1 = c[mt][nt][rr * 2 + 1] + b1[nt];
                s1 = fmaf(h0, ws0[nt], fmaf(h1, ws1[nt], s1));
                s2 = fmaf(h0, wd0[nt], fmaf(h1, wd1[nt], s2));
                hh[nt] = h2u(h0, h1);
            }
            s1 += __shfl_xor_sync(0xFFFFFFFFu, s1, 1);
            s1 += __shfl_xor_sync(0xFFFFFFFFu, s1, 2);
            s2 += __shfl_xor_sync(0xFFFFFFFFu, s2, 1);
            s2 += __shfl_xor_sync(0xFFFFFFFFu, s2, 2);

            long row = m_warp + mt * 16 + rr * 8 + g;
            if (row < N_NODES) {
                unsigned* rp = (unsigned*)g_hh + (size_t)row * ROWW;
#pragma unroll
                for (int nt = 0; nt < 6; nt++)
                    rp[nt * 4 + tig] = hh[nt];
                if (tig == 0) {
                    ((float*)rp)[24] = s1;   // ssrc rides in the h cache line
                    g_sdst[row] = s2;
                }
            }
        }
    }
}

// ---------------------------------------------------------------------------
// Single-pass exclusive scan of g_cnt -> g_off/g_cursor (decoupled lookback).
// ---------------------------------------------------------------------------
__global__ void __launch_bounds__(1024) k_scan()
{
    __shared__ int wsum[32];
    __shared__ int s_prefix;
    int tid = threadIdx.x, bid = blockIdx.x;
    int gid = bid * 1024 + tid;
    int lane = tid & 31, wid = tid >> 5;
    int x = (gid < N_NODES) ? g_cnt[gid] : 0;
    int incl = x;
#pragma unroll
    for (int o = 1; o < 32; o <<= 1) {
        int y = __shfl_up_sync(0xFFFFFFFFu, incl, o);
        if (lane >= o) incl += y;
    }
    if (lane == 31) wsum[wid] = incl;
    __syncthreads();
    if (wid == 0) {
        int v = wsum[lane];
#pragma unroll
        for (int o = 1; o < 32; o <<= 1) {
            int y = __shfl_up_sync(0xFFFFFFFFu, v, o);
            if (lane >= o) v += y;
        }
        wsum[lane] = v;
    }
    __syncthreads();
    int wofs = (wid > 0) ? wsum[wid - 1] : 0;
    int total = wsum[31];

    if (tid == 0) {
        if (bid == 0) {
            atomicExch(&g_state[0], (2ULL << 62) | (unsigned)total);
            s_prefix = 0;
        } else {
            atomicExch(&g_state[bid], (1ULL << 62) | (unsigned)total);
            int run = 0;
            int j = bid - 1;
            while (true) {
                unsigned long long v = atomicAdd(&g_state[j], 0ULL);
                unsigned f = (unsigned)(v >> 62);
                if (f == 0) { __nanosleep(20); continue; }
                run += (int)(v & 0xFFFFFFFFULL);
                if (f == 2) break;
                j--;
            }
            atomicExch(&g_state[bid], (2ULL << 62) | (unsigned)(run + total));
            s_prefix = run;
        }
    }
    __syncthreads();
    if (gid < N_NODES) {
        int o = s_prefix + wofs + incl - x;
        g_off[gid] = o;
        g_cursor[gid] = o;
    }
}

// ---------------------------------------------------------------------------
// Scatter-lite: sort src indices by dst (2 sequential loads, 1 cursor atomic,
// 1 random 4B store).
// ---------------------------------------------------------------------------
__global__ void k_scatter(const int* __restrict__ src, const int* __restrict__ dst)
{
    int e = blockIdx.x * blockDim.x + threadIdx.x;
    if (e >= N_EDGES) return;
    int s = src[e], d = dst[e];
    int pos = atomicAdd(&g_cursor[d], 1);
    g_srt[pos] = s;
}

// ---------------------------------------------------------------------------
// Gather (join): 8 threads/node; logit+exp computed in-kernel (sdst[n]+b once
// per node; ssrc[s] rides in the h-row's cache line at word 24).
// ---------------------------------------------------------------------------
__global__ void __launch_bounds__(256) k_gather(float* __restrict__ out,
                                                const float* __restrict__ attnb)
{
    int gt = blockIdx.x * blockDim.x + threadIdx.x;
    int n = gt >> 3;
    int t = gt & 7;
    if (n >= N_NODES) return;
    int start = g_off[n];
    int deg = g_cnt[n];
    float sdn = g_sdst[n] + attnb[0];

    const unsigned* H = (const unsigned*)g_hh;  // row = 32 u32 (128B)
    int hb = t * 3;

    float a0 = 0.f, a1 = 0.f, a2 = 0.f, a3 = 0.f, a4 = 0.f, a5 = 0.f, den = 0.f;

    int k = 0;
    for (; k + 2 <= deg; k += 2) {
        int s0 = g_srt[start + k];
        int s1 = g_srt[start + k + 1];
        const unsigned* r0 = H + s0 * ROWW;
        const unsigned* r1 = H + s1 * ROWW;
        float sv0 = __uint_as_float(r0[24]);
        float sv1 = __uint_as_float(r1[24]);
        unsigned w00 = r0[hb], w01 = r0[hb + 1], w02 = r0[hb + 2];
        unsigned w10 = r1[hb], w11 = r1[hb + 1], w12 = r1[hb + 2];
        float v0 = sv0 + sdn;
        float v1 = sv1 + sdn;
        v0 = (v0 > 0.0f) ? v0 : 0.2f * v0;
        v1 = (v1 > 0.0f) ? v1 : 0.2f * v1;
        float ex0 = __expf(v0);
        float ex1 = __expf(v1);
        den += ex0 + ex1;
        float2 f;
        f = __half22float2(*(__half2*)&w00); a0 = fmaf(f.x, ex0, a0); a1 = fmaf(f.y, ex0, a1);
        f = __half22float2(*(__half2*)&w01); a2 = fmaf(f.x, ex0, a2); a3 = fmaf(f.y, ex0, a3);
        f = __half22float2(*(__half2*)&w02); a4 = fmaf(f.x, ex0, a4); a5 = fmaf(f.y, ex0, a5);
        f = __half22float2(*(__half2*)&w10); a0 = fmaf(f.x, ex1, a0); a1 = fmaf(f.y, ex1, a1);
        f = __half22float2(*(__half2*)&w11); a2 = fmaf(f.x, ex1, a2); a3 = fmaf(f.y, ex1, a3);
        f = __half22float2(*(__half2*)&w12); a4 = fmaf(f.x, ex1, a4); a5 = fmaf(f.y, ex1, a5);
    }
    if (k < deg) {
        int s0 = g_srt[start + k];
        const unsigned* r0 = H + s0 * ROWW;
        float sv0 = __uint_as_float(r0[24]);
        unsigned w00 = r0[hb], w01 = r0[hb + 1], w02 = r0[hb + 2];
        float v0 = sv0 + sdn;
        v0 = (v0 > 0.0f) ? v0 : 0.2f * v0;
        float ex0 = __expf(v0);
        den += ex0;
        float2 f;
        f = __half22float2(*(__half2*)&w00); a0 = fmaf(f.x, ex0, a0); a1 = fmaf(f.y, ex0, a1);
        f = __half22float2(*(__half2*)&w01); a2 = fmaf(f.x, ex0, a2); a3 = fmaf(f.y, ex0, a3);
        f = __half22float2(*(__half2*)&w02); a4 = fmaf(f.x, ex0, a4); a5 = fmaf(f.y, ex0, a5);
    }

    float inv = (deg > 0) ? 1.0f / den : 0.0f;
    float2* op = (float2*)(out + (size_t)n * OUT_F + t * 6);
    op[0] = make_float2(a0 * inv, a1 * inv);
    op[1] = make_float2(a2 * inv, a3 * inv);
    op[2] = make_float2(a4 * inv, a5 * inv);

    // Restore zero-invariants for the next graph replay (warp-safe: the
    // g_cnt load above is issued for the whole warp before any lane stores).
    if (t == 0) g_cnt[n] = 0;
    if (t == 1 && n < NBLK_SCAN) g_state[n] = 0ULL;
}

// ---------------------------------------------------------------------------
// Launcher: two concurrent dependency chains inside the captured graph.
//   branch A (stream 0): hist -> scan -> scatter      (memory/atomic bound)
//   branch B (s_gemm)  : gemm                         (tensor-core bound)
//   join    (stream 0) : gather
// Stream/events are host-side infra created once; the captured GPU work is
// identical on every call and allocation-free.
// ---------------------------------------------------------------------------
extern "C" void kernel_launch(void* const* d_in, const int* in_sizes, int n_in,
                              void* d_out, int out_size)
{
    const float* feat  = (const float*)d_in[0];
    const float* Ww    = (const float*)d_in[1];
    const float* Wb    = (const float*)d_in[2];
    const float* attnw = (const float*)d_in[3];
    const float* attnb = (const float*)d_in[4];
    const int*   src   = (const int*)d_in[5];
    const int*   dst   = (const int*)d_in[6];
    float* out = (float*)d_out;

    static cudaStream_t s_gemm = nullptr;
    static cudaEvent_t ev_fork = nullptr, ev_join = nullptr;
    if (s_gemm == nullptr) {
        cudaStreamCreateWithFlags(&s_gemm, cudaStreamNonBlocking);
        cudaEventCreateWithFlags(&ev_fork, cudaEventDisableTiming);
        cudaEventCreateWithFlags(&ev_join, cudaEventDisableTiming);
    }

    // Fork: branch B (gemm) runs concurrently with branch A.
    cudaEventRecord(ev_fork, 0);
    cudaStreamWaitEvent(s_gemm, ev_fork, 0);
    k_gemm<<<(N_NODES + 255) / 256, 256, 0, s_gemm>>>(feat, Ww, Wb, attnw);

    // Branch A on the main stream.
    k_hist<<<(N_EDGES + 255) / 256, 256>>>(dst);
    k_scan<<<NBLK_SCAN, 1024>>>();
    k_scatter<<<(N_EDGES + 255) / 256, 256>>>(src, dst);

    // Join, then gather.
    cudaEventRecord(ev_join, s_gemm);
    cudaStreamWaitEvent(0, ev_join, 0);
    k_gather<<<(N_NODES * 8 + 255) / 256, 256>>>(out, attnb);
}